// round 10
// baseline (speedup 1.0000x reference)
#include <cuda_runtime.h>
#include <cuda_fp16.h>
#include <cuda_fp8.h>

// Problem constants (match reference_code)
#define N_EMB 8192
#define D_EMB 512
#define T_TRIP 262144
#define MARGIN 1.0f

// Scratch: normalized embeddings in fp8 e4m3 (4 MB, L2-resident) + accumulator.
__device__ unsigned char g_norm8[N_EMB * D_EMB];
__device__ float g_acc;

static __device__ __forceinline__ __half2 fp8x2_to_h2(__nv_fp8x2_storage_t x) {
    __half2_raw hr = __nv_cvt_fp8x2_to_halfraw2(x, __NV_E4M3);
    return *reinterpret_cast<__half2*>(&hr);
}

static __device__ __forceinline__ unsigned int f4_to_fp8x4(float a, float b, float c, float d) {
    float2 lo = make_float2(a, b), hi = make_float2(c, d);
    unsigned int l = __nv_cvt_float2_to_fp8x2(lo, __NV_SATFINITE, __NV_E4M3);
    unsigned int h = __nv_cvt_float2_to_fp8x2(hi, __NV_SATFINITE, __NV_E4M3);
    return l | (h << 16);
}

// ---------------------------------------------------------------------------
// Kernel 1: row-wise L2 normalize, fp32 -> fp8 e4m3. One WARP per row.
// 256 threads = 8 rows/block, 1024 blocks. No smem, no __syncthreads.
// ---------------------------------------------------------------------------
__global__ void normalize_kernel(const float* __restrict__ emb) {
    const int lane = threadIdx.x & 31;
    const int row  = blockIdx.x * 8 + (threadIdx.x >> 5);
    if (blockIdx.x == 0 && threadIdx.x == 0) g_acc = 0.0f;

    const float4* __restrict__ r = (const float4*)(emb + (size_t)row * D_EMB);
    float4 v[4];
    #pragma unroll
    for (int k = 0; k < 4; k++) v[k] = r[lane + 32 * k];

    float ss = 0.0f;
    #pragma unroll
    for (int k = 0; k < 4; k++)
        ss += v[k].x * v[k].x + v[k].y * v[k].y + v[k].z * v[k].z + v[k].w * v[k].w;
    #pragma unroll
    for (int o = 16; o; o >>= 1) ss += __shfl_xor_sync(0xffffffffu, ss, o);

    const float inv = rsqrtf(ss);

    uint4 out;
    out.x = f4_to_fp8x4(v[0].x * inv, v[0].y * inv, v[0].z * inv, v[0].w * inv);
    out.y = f4_to_fp8x4(v[1].x * inv, v[1].y * inv, v[1].z * inv, v[1].w * inv);
    out.z = f4_to_fp8x4(v[2].x * inv, v[2].y * inv, v[2].z * inv, v[2].w * inv);
    out.w = f4_to_fp8x4(v[3].x * inv, v[3].y * inv, v[3].z * inv, v[3].w * inv);

    // 32 lanes x 16B = 512B = one row
    ((uint4*)(g_norm8 + (size_t)row * D_EMB))[lane] = out;
}

// ---------------------------------------------------------------------------
// Kernel 2: one warp per triplet (contiguous chunk per warp).
// s = a . (n - p); loss = relu(s + MARGIN); accumulate.
// One LDG.128 per lane per vector (16 fp8 elements), 3 loads per triplet.
// ---------------------------------------------------------------------------
__global__ void triplet_kernel(const int* __restrict__ ind_a,
                               const int* __restrict__ ind_p,
                               const int* __restrict__ ind_n) {
    const int lane   = threadIdx.x & 31;
    const int warp   = (blockIdx.x * blockDim.x + threadIdx.x) >> 5;
    const int nwarps = (gridDim.x * blockDim.x) >> 5;

    const int chunk = (T_TRIP + nwarps - 1) / nwarps;
    const int t0 = warp * chunk;
    const int t1 = (t0 + chunk < T_TRIP) ? (t0 + chunk) : T_TRIP;

    const uint4* __restrict__ base = (const uint4*)g_norm8;  // row = 32 uint4

    float local = 0.0f;
    for (int t = t0; t < t1; t++) {
        const int ia = ind_a[t];
        const int ip = ind_p[t];
        const int in = ind_n[t];

        const uint4 va = base[ia * 32 + lane];
        const uint4 vp = base[ip * 32 + lane];
        const uint4 vn = base[in * 32 + lane];

        const __nv_fp8x2_storage_t* pa = (const __nv_fp8x2_storage_t*)&va;
        const __nv_fp8x2_storage_t* pp = (const __nv_fp8x2_storage_t*)&vp;
        const __nv_fp8x2_storage_t* pn = (const __nv_fp8x2_storage_t*)&vn;

        __half2 acc0 = __float2half2_rn(0.0f);
        __half2 acc1 = __float2half2_rn(0.0f);
        #pragma unroll
        for (int j = 0; j < 4; j++) {
            const __half2 a0 = fp8x2_to_h2(pa[j]);
            const __half2 d0 = __hsub2(fp8x2_to_h2(pn[j]), fp8x2_to_h2(pp[j]));
            acc0 = __hfma2(a0, d0, acc0);
            const __half2 a1 = fp8x2_to_h2(pa[j + 4]);
            const __half2 d1 = __hsub2(fp8x2_to_h2(pn[j + 4]), fp8x2_to_h2(pp[j + 4]));
            acc1 = __hfma2(a1, d1, acc1);
        }
        const float2 f = __half22float2(__hadd2(acc0, acc1));
        float s = f.x + f.y;

        #pragma unroll
        for (int o = 16; o; o >>= 1) s += __shfl_xor_sync(0xffffffffu, s, o);
        if (lane == 0) local += fmaxf(s + MARGIN, 0.0f);
    }

    __shared__ float sm[8];
    if (lane == 0) sm[threadIdx.x >> 5] = local;
    __syncthreads();
    if (threadIdx.x == 0) {
        float v = 0.0f;
        #pragma unroll
        for (int i = 0; i < 8; i++) v += sm[i];
        atomicAdd(&g_acc, v);
    }
}

// ---------------------------------------------------------------------------
// Kernel 3: finalize mean.
// ---------------------------------------------------------------------------
__global__ void finalize_kernel(float* __restrict__ out) {
    *out = g_acc * (1.0f / (float)T_TRIP);
}

extern "C" void kernel_launch(void* const* d_in, const int* in_sizes, int n_in,
                              void* d_out, int out_size) {
    const float* emb   = (const float*)d_in[0];
    const int*   ind_a = (const int*)d_in[1];
    const int*   ind_p = (const int*)d_in[2];
    const int*   ind_n = (const int*)d_in[3];
    float* out = (float*)d_out;

    normalize_kernel<<<N_EMB / 8, 256>>>(emb);
    triplet_kernel<<<1184, 256>>>(ind_a, ind_p, ind_n);
    finalize_kernel<<<1, 1>>>(out);
}

// round 11
// speedup vs baseline: 1.0477x; 1.0477x over previous
#include <cuda_runtime.h>
#include <cuda_fp16.h>
#include <cuda_fp8.h>

// Problem constants (match reference_code)
#define N_EMB 8192
#define D_EMB 512
#define T_TRIP 262144
#define MARGIN 1.0f

// Scratch: normalized embeddings in fp8 e4m3 (4 MB, L2-resident) + accumulator.
__device__ unsigned char g_norm8[N_EMB * D_EMB];
__device__ float g_acc;

static __device__ __forceinline__ __half2 fp8x2_to_h2(__nv_fp8x2_storage_t x) {
    __half2_raw hr = __nv_cvt_fp8x2_to_halfraw2(x, __NV_E4M3);
    return *reinterpret_cast<__half2*>(&hr);
}

static __device__ __forceinline__ unsigned int f4_to_fp8x4(float a, float b, float c, float d) {
    float2 lo = make_float2(a, b), hi = make_float2(c, d);
    unsigned int l = __nv_cvt_float2_to_fp8x2(lo, __NV_SATFINITE, __NV_E4M3);
    unsigned int h = __nv_cvt_float2_to_fp8x2(hi, __NV_SATFINITE, __NV_E4M3);
    return l | (h << 16);
}

// ---------------------------------------------------------------------------
// Kernel 1: row-wise L2 normalize, fp32 -> fp8 e4m3. One WARP per row.
// 256 threads = 8 rows/block, 1024 blocks. No smem, no __syncthreads.
// ---------------------------------------------------------------------------
__global__ void normalize_kernel(const float* __restrict__ emb) {
    const int lane = threadIdx.x & 31;
    const int row  = blockIdx.x * 8 + (threadIdx.x >> 5);
    if (blockIdx.x == 0 && threadIdx.x == 0) g_acc = 0.0f;

    const float4* __restrict__ r = (const float4*)(emb + (size_t)row * D_EMB);
    float4 v[4];
    #pragma unroll
    for (int k = 0; k < 4; k++) v[k] = r[lane + 32 * k];

    float ss = 0.0f;
    #pragma unroll
    for (int k = 0; k < 4; k++)
        ss += v[k].x * v[k].x + v[k].y * v[k].y + v[k].z * v[k].z + v[k].w * v[k].w;
    #pragma unroll
    for (int o = 16; o; o >>= 1) ss += __shfl_xor_sync(0xffffffffu, ss, o);

    const float inv = rsqrtf(ss);

    uint4 out;
    out.x = f4_to_fp8x4(v[0].x * inv, v[0].y * inv, v[0].z * inv, v[0].w * inv);
    out.y = f4_to_fp8x4(v[1].x * inv, v[1].y * inv, v[1].z * inv, v[1].w * inv);
    out.z = f4_to_fp8x4(v[2].x * inv, v[2].y * inv, v[2].z * inv, v[2].w * inv);
    out.w = f4_to_fp8x4(v[3].x * inv, v[3].y * inv, v[3].z * inv, v[3].w * inv);

    // 32 lanes x 16B = 512B = one row
    ((uint4*)(g_norm8 + (size_t)row * D_EMB))[lane] = out;
}

// ---------------------------------------------------------------------------
// Kernel 2: one warp per triplet (contiguous chunk per warp).
// s = a . (n - p); loss = relu(s + MARGIN); accumulate.
// One LDG.128 per lane per vector (16 fp8 elements), 3 loads per triplet.
// ---------------------------------------------------------------------------
__global__ void triplet_kernel(const int* __restrict__ ind_a,
                               const int* __restrict__ ind_p,
                               const int* __restrict__ ind_n) {
    const int lane   = threadIdx.x & 31;
    const int warp   = (blockIdx.x * blockDim.x + threadIdx.x) >> 5;
    const int nwarps = (gridDim.x * blockDim.x) >> 5;

    const int chunk = (T_TRIP + nwarps - 1) / nwarps;
    const int t0 = warp * chunk;
    const int t1 = (t0 + chunk < T_TRIP) ? (t0 + chunk) : T_TRIP;

    const uint4* __restrict__ base = (const uint4*)g_norm8;  // row = 32 uint4

    float local = 0.0f;
    for (int t = t0; t < t1; t++) {
        const int ia = ind_a[t];
        const int ip = ind_p[t];
        const int in = ind_n[t];

        const uint4 va = base[ia * 32 + lane];
        const uint4 vp = base[ip * 32 + lane];
        const uint4 vn = base[in * 32 + lane];

        const __nv_fp8x2_storage_t* pa = (const __nv_fp8x2_storage_t*)&va;
        const __nv_fp8x2_storage_t* pp = (const __nv_fp8x2_storage_t*)&vp;
        const __nv_fp8x2_storage_t* pn = (const __nv_fp8x2_storage_t*)&vn;

        __half2 acc0 = __float2half2_rn(0.0f);
        __half2 acc1 = __float2half2_rn(0.0f);
        #pragma unroll
        for (int j = 0; j < 4; j++) {
            const __half2 a0 = fp8x2_to_h2(pa[j]);
            const __half2 d0 = __hsub2(fp8x2_to_h2(pn[j]), fp8x2_to_h2(pp[j]));
            acc0 = __hfma2(a0, d0, acc0);
            const __half2 a1 = fp8x2_to_h2(pa[j + 4]);
            const __half2 d1 = __hsub2(fp8x2_to_h2(pn[j + 4]), fp8x2_to_h2(pp[j + 4]));
            acc1 = __hfma2(a1, d1, acc1);
        }
        const float2 f = __half22float2(__hadd2(acc0, acc1));
        float s = f.x + f.y;

        #pragma unroll
        for (int o = 16; o; o >>= 1) s += __shfl_xor_sync(0xffffffffu, s, o);
        if (lane == 0) local += fmaxf(s + MARGIN, 0.0f);
    }

    __shared__ float sm[8];
    if (lane == 0) sm[threadIdx.x >> 5] = local;
    __syncthreads();
    if (threadIdx.x == 0) {
        float v = 0.0f;
        #pragma unroll
        for (int i = 0; i < 8; i++) v += sm[i];
        atomicAdd(&g_acc, v);
    }
}

// ---------------------------------------------------------------------------
// Kernel 3: finalize mean.
// ---------------------------------------------------------------------------
__global__ void finalize_kernel(float* __restrict__ out) {
    *out = g_acc * (1.0f / (float)T_TRIP);
}

extern "C" void kernel_launch(void* const* d_in, const int* in_sizes, int n_in,
                              void* d_out, int out_size) {
    const float* emb   = (const float*)d_in[0];
    const int*   ind_a = (const int*)d_in[1];
    const int*   ind_p = (const int*)d_in[2];
    const int*   ind_n = (const int*)d_in[3];
    float* out = (float*)d_out;

    normalize_kernel<<<N_EMB / 8, 256>>>(emb);
    triplet_kernel<<<1184, 256>>>(ind_a, ind_p, ind_n);
    finalize_kernel<<<1, 1>>>(out);
}

// round 12
// speedup vs baseline: 1.0659x; 1.0174x over previous
#include <cuda_runtime.h>
#include <cuda_fp16.h>
#include <cuda_fp8.h>

// Problem constants (match reference_code)
#define N_EMB 8192
#define D_EMB 512
#define T_TRIP 262144
#define MARGIN 1.0f

// Scratch: normalized embeddings in fp8 e4m3 (4 MB, L2-resident) + accumulator.
__device__ unsigned char g_norm8[N_EMB * D_EMB];
__device__ float g_acc;

static __device__ __forceinline__ __half2 fp8x2_to_h2(__nv_fp8x2_storage_t x) {
    __half2_raw hr = __nv_cvt_fp8x2_to_halfraw2(x, __NV_E4M3);
    return *reinterpret_cast<__half2*>(&hr);
}

static __device__ __forceinline__ unsigned int f4_to_fp8x4(float a, float b, float c, float d) {
    float2 lo = make_float2(a, b), hi = make_float2(c, d);
    unsigned int l = __nv_cvt_float2_to_fp8x2(lo, __NV_SATFINITE, __NV_E4M3);
    unsigned int h = __nv_cvt_float2_to_fp8x2(hi, __NV_SATFINITE, __NV_E4M3);
    return l | (h << 16);
}

// ---------------------------------------------------------------------------
// Kernel 1: row-wise L2 normalize, fp32 -> fp8 e4m3. One WARP per row.
// 256 threads = 8 rows/block, 1024 blocks. No smem, no __syncthreads.
// ---------------------------------------------------------------------------
__global__ void normalize_kernel(const float* __restrict__ emb) {
    const int lane = threadIdx.x & 31;
    const int row  = blockIdx.x * 8 + (threadIdx.x >> 5);
    if (blockIdx.x == 0 && threadIdx.x == 0) g_acc = 0.0f;

    const float4* __restrict__ r = (const float4*)(emb + (size_t)row * D_EMB);
    float4 v[4];
    #pragma unroll
    for (int k = 0; k < 4; k++) v[k] = r[lane + 32 * k];

    float ss = 0.0f;
    #pragma unroll
    for (int k = 0; k < 4; k++)
        ss += v[k].x * v[k].x + v[k].y * v[k].y + v[k].z * v[k].z + v[k].w * v[k].w;
    #pragma unroll
    for (int o = 16; o; o >>= 1) ss += __shfl_xor_sync(0xffffffffu, ss, o);

    const float inv = rsqrtf(ss);

    uint4 out;
    out.x = f4_to_fp8x4(v[0].x * inv, v[0].y * inv, v[0].z * inv, v[0].w * inv);
    out.y = f4_to_fp8x4(v[1].x * inv, v[1].y * inv, v[1].z * inv, v[1].w * inv);
    out.z = f4_to_fp8x4(v[2].x * inv, v[2].y * inv, v[2].z * inv, v[2].w * inv);
    out.w = f4_to_fp8x4(v[3].x * inv, v[3].y * inv, v[3].z * inv, v[3].w * inv);

    // 32 lanes x 16B = 512B = one row
    ((uint4*)(g_norm8 + (size_t)row * D_EMB))[lane] = out;
}

// ---------------------------------------------------------------------------
// Kernel 2: one warp per triplet (contiguous chunk per warp).
// s = a . (n - p); loss = relu(s + MARGIN); accumulate.
// One LDG.128 per lane per vector (16 fp8 elements), 3 loads per triplet.
// ---------------------------------------------------------------------------
__global__ void triplet_kernel(const int* __restrict__ ind_a,
                               const int* __restrict__ ind_p,
                               const int* __restrict__ ind_n) {
    const int lane   = threadIdx.x & 31;
    const int warp   = (blockIdx.x * blockDim.x + threadIdx.x) >> 5;
    const int nwarps = (gridDim.x * blockDim.x) >> 5;

    const int chunk = (T_TRIP + nwarps - 1) / nwarps;
    const int t0 = warp * chunk;
    const int t1 = (t0 + chunk < T_TRIP) ? (t0 + chunk) : T_TRIP;

    const uint4* __restrict__ base = (const uint4*)g_norm8;  // row = 32 uint4

    float local = 0.0f;
    for (int t = t0; t < t1; t++) {
        const int ia = ind_a[t];
        const int ip = ind_p[t];
        const int in = ind_n[t];

        const uint4 va = base[ia * 32 + lane];
        const uint4 vp = base[ip * 32 + lane];
        const uint4 vn = base[in * 32 + lane];

        const __nv_fp8x2_storage_t* pa = (const __nv_fp8x2_storage_t*)&va;
        const __nv_fp8x2_storage_t* pp = (const __nv_fp8x2_storage_t*)&vp;
        const __nv_fp8x2_storage_t* pn = (const __nv_fp8x2_storage_t*)&vn;

        __half2 acc0 = __float2half2_rn(0.0f);
        __half2 acc1 = __float2half2_rn(0.0f);
        #pragma unroll
        for (int j = 0; j < 4; j++) {
            const __half2 a0 = fp8x2_to_h2(pa[j]);
            const __half2 d0 = __hsub2(fp8x2_to_h2(pn[j]), fp8x2_to_h2(pp[j]));
            acc0 = __hfma2(a0, d0, acc0);
            const __half2 a1 = fp8x2_to_h2(pa[j + 4]);
            const __half2 d1 = __hsub2(fp8x2_to_h2(pn[j + 4]), fp8x2_to_h2(pp[j + 4]));
            acc1 = __hfma2(a1, d1, acc1);
        }
        const float2 f = __half22float2(__hadd2(acc0, acc1));
        float s = f.x + f.y;

        #pragma unroll
        for (int o = 16; o; o >>= 1) s += __shfl_xor_sync(0xffffffffu, s, o);
        if (lane == 0) local += fmaxf(s + MARGIN, 0.0f);
    }

    __shared__ float sm[8];
    if (lane == 0) sm[threadIdx.x >> 5] = local;
    __syncthreads();
    if (threadIdx.x == 0) {
        float v = 0.0f;
        #pragma unroll
        for (int i = 0; i < 8; i++) v += sm[i];
        atomicAdd(&g_acc, v);
    }
}

// ---------------------------------------------------------------------------
// Kernel 3: finalize mean.
// ---------------------------------------------------------------------------
__global__ void finalize_kernel(float* __restrict__ out) {
    *out = g_acc * (1.0f / (float)T_TRIP);
}

extern "C" void kernel_launch(void* const* d_in, const int* in_sizes, int n_in,
                              void* d_out, int out_size) {
    const float* emb   = (const float*)d_in[0];
    const int*   ind_a = (const int*)d_in[1];
    const int*   ind_p = (const int*)d_in[2];
    const int*   ind_n = (const int*)d_in[3];
    float* out = (float*)d_out;

    normalize_kernel<<<N_EMB / 8, 256>>>(emb);
    triplet_kernel<<<1184, 256>>>(ind_a, ind_p, ind_n);
    finalize_kernel<<<1, 1>>>(out);
}

// round 13
// speedup vs baseline: 1.1202x; 1.0510x over previous
#include <cuda_runtime.h>
#include <cuda_fp16.h>
#include <cuda_fp8.h>

// Problem constants (match reference_code)
#define N_EMB 8192
#define D_EMB 512
#define T_TRIP 262144
#define MARGIN 1.0f

// Scratch: normalized embeddings in fp8 e4m3 (4 MB, L2-resident) + accumulator.
__device__ unsigned char g_norm8[N_EMB * D_EMB];
__device__ float g_acc;

static __device__ __forceinline__ __half2 fp8x2_to_h2(__nv_fp8x2_storage_t x) {
    __half2_raw hr = __nv_cvt_fp8x2_to_halfraw2(x, __NV_E4M3);
    return *reinterpret_cast<__half2*>(&hr);
}

static __device__ __forceinline__ unsigned int f4_to_fp8x4(float a, float b, float c, float d) {
    float2 lo = make_float2(a, b), hi = make_float2(c, d);
    unsigned int l = __nv_cvt_float2_to_fp8x2(lo, __NV_SATFINITE, __NV_E4M3);
    unsigned int h = __nv_cvt_float2_to_fp8x2(hi, __NV_SATFINITE, __NV_E4M3);
    return l | (h << 16);
}

// ---------------------------------------------------------------------------
// Kernel 1: row-wise L2 normalize, fp32 -> fp8 e4m3. One WARP per row.
// 256 threads = 8 rows/block, 1024 blocks. No smem, no __syncthreads.
// ---------------------------------------------------------------------------
__global__ void normalize_kernel(const float* __restrict__ emb) {
    const int lane = threadIdx.x & 31;
    const int row  = blockIdx.x * 8 + (threadIdx.x >> 5);
    if (blockIdx.x == 0 && threadIdx.x == 0) g_acc = 0.0f;

    const float4* __restrict__ r = (const float4*)(emb + (size_t)row * D_EMB);
    float4 v[4];
    #pragma unroll
    for (int k = 0; k < 4; k++) v[k] = r[lane + 32 * k];

    float ss = 0.0f;
    #pragma unroll
    for (int k = 0; k < 4; k++)
        ss += v[k].x * v[k].x + v[k].y * v[k].y + v[k].z * v[k].z + v[k].w * v[k].w;
    #pragma unroll
    for (int o = 16; o; o >>= 1) ss += __shfl_xor_sync(0xffffffffu, ss, o);

    const float inv = rsqrtf(ss);

    uint4 out;
    out.x = f4_to_fp8x4(v[0].x * inv, v[0].y * inv, v[0].z * inv, v[0].w * inv);
    out.y = f4_to_fp8x4(v[1].x * inv, v[1].y * inv, v[1].z * inv, v[1].w * inv);
    out.z = f4_to_fp8x4(v[2].x * inv, v[2].y * inv, v[2].z * inv, v[2].w * inv);
    out.w = f4_to_fp8x4(v[3].x * inv, v[3].y * inv, v[3].z * inv, v[3].w * inv);

    // 32 lanes x 16B = 512B = one row
    ((uint4*)(g_norm8 + (size_t)row * D_EMB))[lane] = out;
}

// ---------------------------------------------------------------------------
// Kernel 2: one warp per triplet (contiguous chunk per warp).
// s = a . (n - p); loss = relu(s + MARGIN); accumulate.
// One LDG.128 per lane per vector (16 fp8 elements), 3 loads per triplet.
// ---------------------------------------------------------------------------
__global__ void triplet_kernel(const int* __restrict__ ind_a,
                               const int* __restrict__ ind_p,
                               const int* __restrict__ ind_n) {
    const int lane   = threadIdx.x & 31;
    const int warp   = (blockIdx.x * blockDim.x + threadIdx.x) >> 5;
    const int nwarps = (gridDim.x * blockDim.x) >> 5;

    const int chunk = (T_TRIP + nwarps - 1) / nwarps;
    const int t0 = warp * chunk;
    const int t1 = (t0 + chunk < T_TRIP) ? (t0 + chunk) : T_TRIP;

    const uint4* __restrict__ base = (const uint4*)g_norm8;  // row = 32 uint4

    float local = 0.0f;
    for (int t = t0; t < t1; t++) {
        const int ia = ind_a[t];
        const int ip = ind_p[t];
        const int in = ind_n[t];

        const uint4 va = base[ia * 32 + lane];
        const uint4 vp = base[ip * 32 + lane];
        const uint4 vn = base[in * 32 + lane];

        const __nv_fp8x2_storage_t* pa = (const __nv_fp8x2_storage_t*)&va;
        const __nv_fp8x2_storage_t* pp = (const __nv_fp8x2_storage_t*)&vp;
        const __nv_fp8x2_storage_t* pn = (const __nv_fp8x2_storage_t*)&vn;

        __half2 acc0 = __float2half2_rn(0.0f);
        __half2 acc1 = __float2half2_rn(0.0f);
        #pragma unroll
        for (int j = 0; j < 4; j++) {
            const __half2 a0 = fp8x2_to_h2(pa[j]);
            const __half2 d0 = __hsub2(fp8x2_to_h2(pn[j]), fp8x2_to_h2(pp[j]));
            acc0 = __hfma2(a0, d0, acc0);
            const __half2 a1 = fp8x2_to_h2(pa[j + 4]);
            const __half2 d1 = __hsub2(fp8x2_to_h2(pn[j + 4]), fp8x2_to_h2(pp[j + 4]));
            acc1 = __hfma2(a1, d1, acc1);
        }
        const float2 f = __half22float2(__hadd2(acc0, acc1));
        float s = f.x + f.y;

        #pragma unroll
        for (int o = 16; o; o >>= 1) s += __shfl_xor_sync(0xffffffffu, s, o);
        if (lane == 0) local += fmaxf(s + MARGIN, 0.0f);
    }

    __shared__ float sm[8];
    if (lane == 0) sm[threadIdx.x >> 5] = local;
    __syncthreads();
    if (threadIdx.x == 0) {
        float v = 0.0f;
        #pragma unroll
        for (int i = 0; i < 8; i++) v += sm[i];
        atomicAdd(&g_acc, v);
    }
}

// ---------------------------------------------------------------------------
// Kernel 3: finalize mean.
// ---------------------------------------------------------------------------
__global__ void finalize_kernel(float* __restrict__ out) {
    *out = g_acc * (1.0f / (float)T_TRIP);
}

extern "C" void kernel_launch(void* const* d_in, const int* in_sizes, int n_in,
                              void* d_out, int out_size) {
    const float* emb   = (const float*)d_in[0];
    const int*   ind_a = (const int*)d_in[1];
    const int*   ind_p = (const int*)d_in[2];
    const int*   ind_n = (const int*)d_in[3];
    float* out = (float*)d_out;

    normalize_kernel<<<N_EMB / 8, 256>>>(emb);
    triplet_kernel<<<1184, 256>>>(ind_a, ind_p, ind_n);
    finalize_kernel<<<1, 1>>>(out);
}